// round 1
// baseline (speedup 1.0000x reference)
#include <cuda_runtime.h>
#include <cstdint>

// Tile config: 128x128 block tile, K-tile 16, 8x8 per thread, 256 threads.
#define TBM 128
#define TBN 128
#define TBK 16
#define TTM 8
#define TTN 8
#define NTHR 256

// Fixed problem: B=4096, D=1024, H=4096. Scratch as device globals (no allocs).
__device__ float g_h[4096ull * 4096ull];    // relu(zp @ W1m + b1)
__device__ float g_res[4096ull * 2048ull];  // h @ W2m + b2
__device__ int   g_inv[4096];               // argsort(permutation)

// ---- packed f32x2 helpers (sm_103a: full-rate fp32 only via fma.rn.f32x2) ----
__device__ __forceinline__ unsigned long long pack_dup(float x) {
    unsigned long long d;
    unsigned int u = __float_as_uint(x);
    asm("mov.b64 %0, {%1, %1};" : "=l"(d) : "r"(u));
    return d;
}
__device__ __forceinline__ unsigned long long pack2(float x, float y) {
    unsigned long long d;
    unsigned int ux = __float_as_uint(x), uy = __float_as_uint(y);
    asm("mov.b64 %0, {%1, %2};" : "=l"(d) : "r"(ux), "r"(uy));
    return d;
}
__device__ __forceinline__ void unpack2(unsigned long long d, float& x, float& y) {
    unsigned int ux, uy;
    asm("mov.b64 {%0, %1}, %2;" : "=r"(ux), "=r"(uy) : "l"(d));
    x = __uint_as_float(ux);
    y = __uint_as_float(uy);
}
__device__ __forceinline__ void ffma2(unsigned long long& d,
                                      unsigned long long a, unsigned long long b) {
    asm("fma.rn.f32x2 %0, %1, %2, %0;" : "+l"(d) : "l"(a), "l"(b));
}

__global__ void build_inv(const int* __restrict__ perm, int D) {
    int d = blockIdx.x * blockDim.x + threadIdx.x;
    if (d < D) g_inv[perm[d]] = d;
}

// =====================================================================
// GEMM1: g_h = relu(zp @ (W1*M1) + b1),  zp[i,k] = z[i, perm[k]]
// M1[k,j] = ((j % (D-1)) >= k)
// M=B, N=H, K=D
// =====================================================================
__global__ __launch_bounds__(NTHR, 2) void gemm1_kernel(
    const float* __restrict__ z, const float* __restrict__ W1,
    const float* __restrict__ b1, const int* __restrict__ perm,
    int M, int N, int K, int Dm1)
{
    __shared__ float As[TBK][TBM + 4];
    __shared__ float Bs[TBK][TBN];

    const int tid = threadIdx.x;
    const int tx = tid & 15;
    const int ty = tid >> 4;
    const int row0 = blockIdx.y * TBM;
    const int col0 = blockIdx.x * TBN;

    unsigned long long acc[TTM][TTN / 2];
#pragma unroll
    for (int m = 0; m < TTM; m++)
#pragma unroll
        for (int n = 0; n < TTN / 2; n++) acc[m][n] = 0ull;

    // A-load mapping (8 scalars/thread, perm gather)
    int a_m[8], a_k[8];
#pragma unroll
    for (int e = 0; e < 8; e++) {
        int idx = tid + e * NTHR;
        a_m[e] = idx >> 4;
        a_k[e] = idx & 15;
    }
    // B-load mapping (2 float4/thread)
    int b_k[2], b_n[2];
#pragma unroll
    for (int e = 0; e < 2; e++) {
        int idx = tid + e * NTHR;
        b_k[e] = idx >> 5;
        b_n[e] = (idx & 31) << 2;
    }
    // j % (D-1) is constant per thread per component: precompute.
    int jm[2][4];
#pragma unroll
    for (int e = 0; e < 2; e++)
#pragma unroll
        for (int c = 0; c < 4; c++) {
            int j = col0 + b_n[e] + c;
            int r = j;
            while (r >= Dm1) r -= Dm1;
            jm[e][c] = r;
        }

    float  a_reg[8];
    float4 b_reg[2];

    auto loadA = [&](int k0) {
#pragma unroll
        for (int e = 0; e < 8; e++)
            a_reg[e] = z[(size_t)(row0 + a_m[e]) * K + perm[k0 + a_k[e]]];
    };
    auto loadB = [&](int k0) {
#pragma unroll
        for (int e = 0; e < 2; e++) {
            int kg = k0 + b_k[e];
            float4 v = *reinterpret_cast<const float4*>(
                &W1[(size_t)kg * N + col0 + b_n[e]]);
            if (jm[e][0] < kg) v.x = 0.f;
            if (jm[e][1] < kg) v.y = 0.f;
            if (jm[e][2] < kg) v.z = 0.f;
            if (jm[e][3] < kg) v.w = 0.f;
            b_reg[e] = v;
        }
    };
    auto storeAB = [&]() {
#pragma unroll
        for (int e = 0; e < 8; e++) As[a_k[e]][a_m[e]] = a_reg[e];
#pragma unroll
        for (int e = 0; e < 2; e++)
            *reinterpret_cast<float4*>(&Bs[b_k[e]][b_n[e]]) = b_reg[e];
    };

    loadA(0);
    loadB(0);
    storeAB();
    __syncthreads();

    const int nk = K / TBK;
    for (int t = 0; t < nk; t++) {
        const bool has_next = (t + 1 < nk);
        if (has_next) { loadA((t + 1) * TBK); loadB((t + 1) * TBK); }
#pragma unroll
        for (int k = 0; k < TBK; k++) {
            const float4 a0  = *reinterpret_cast<const float4*>(&As[k][ty * TTM]);
            const float4 a1  = *reinterpret_cast<const float4*>(&As[k][ty * TTM + 4]);
            const float4 bb0 = *reinterpret_cast<const float4*>(&Bs[k][tx * TTN]);
            const float4 bb1 = *reinterpret_cast<const float4*>(&Bs[k][tx * TTN + 4]);
            unsigned long long av[8];
            av[0] = pack_dup(a0.x); av[1] = pack_dup(a0.y);
            av[2] = pack_dup(a0.z); av[3] = pack_dup(a0.w);
            av[4] = pack_dup(a1.x); av[5] = pack_dup(a1.y);
            av[6] = pack_dup(a1.z); av[7] = pack_dup(a1.w);
            unsigned long long bv[4];
            bv[0] = pack2(bb0.x, bb0.y); bv[1] = pack2(bb0.z, bb0.w);
            bv[2] = pack2(bb1.x, bb1.y); bv[3] = pack2(bb1.z, bb1.w);
#pragma unroll
            for (int m = 0; m < TTM; m++)
#pragma unroll
                for (int n = 0; n < TTN / 2; n++)
                    ffma2(acc[m][n], av[m], bv[n]);
        }
        __syncthreads();
        if (has_next) { storeAB(); __syncthreads(); }
    }

    // epilogue: + b1, relu, store to g_h
    float bias[TTN];
#pragma unroll
    for (int n = 0; n < TTN; n++) bias[n] = b1[col0 + tx * TTN + n];
#pragma unroll
    for (int m = 0; m < TTM; m++) {
        int r = row0 + ty * TTM + m;
        float v[TTN];
#pragma unroll
        for (int n = 0; n < TTN / 2; n++) unpack2(acc[m][n], v[2 * n], v[2 * n + 1]);
        float4 o0, o1;
        o0.x = fmaxf(v[0] + bias[0], 0.f);
        o0.y = fmaxf(v[1] + bias[1], 0.f);
        o0.z = fmaxf(v[2] + bias[2], 0.f);
        o0.w = fmaxf(v[3] + bias[3], 0.f);
        o1.x = fmaxf(v[4] + bias[4], 0.f);
        o1.y = fmaxf(v[5] + bias[5], 0.f);
        o1.z = fmaxf(v[6] + bias[6], 0.f);
        o1.w = fmaxf(v[7] + bias[7], 0.f);
        float* orow = &g_h[(size_t)r * N + col0 + tx * TTN];
        *reinterpret_cast<float4*>(orow)     = o0;
        *reinterpret_cast<float4*>(orow + 4) = o1;
    }
}

// =====================================================================
// GEMM2: g_res = g_h @ (W2*M2) + b2
// M2[k,j] = ((j % D) > (k % (D-1)))
// M=B, N=2D, K=H
// =====================================================================
__global__ __launch_bounds__(NTHR, 2) void gemm2_kernel(
    const float* __restrict__ W2, const float* __restrict__ b2,
    int M, int N, int K, int D, int Dm1)
{
    __shared__ float As[TBK][TBM + 4];
    __shared__ float Bs[TBK][TBN];

    const int tid = threadIdx.x;
    const int tx = tid & 15;
    const int ty = tid >> 4;
    const int row0 = blockIdx.y * TBM;
    const int col0 = blockIdx.x * TBN;

    unsigned long long acc[TTM][TTN / 2];
#pragma unroll
    for (int m = 0; m < TTM; m++)
#pragma unroll
        for (int n = 0; n < TTN / 2; n++) acc[m][n] = 0ull;

    // A-load mapping (2 float4/thread)
    int a_m4[2], a_kc[2];
#pragma unroll
    for (int e = 0; e < 2; e++) {
        int idx = tid + e * NTHR;
        a_m4[e] = idx >> 2;
        a_kc[e] = (idx & 3) << 2;
    }
    // B-load mapping (2 float4/thread)
    int b_k[2], b_n[2];
#pragma unroll
    for (int e = 0; e < 2; e++) {
        int idx = tid + e * NTHR;
        b_k[e] = idx >> 5;
        b_n[e] = (idx & 31) << 2;
    }
    // (col0 + b_n + c) % D constant per thread: precompute.
    int jd[2][4];
#pragma unroll
    for (int e = 0; e < 2; e++)
#pragma unroll
        for (int c = 0; c < 4; c++) {
            int j = col0 + b_n[e] + c;
            int r = j;
            while (r >= D) r -= D;
            jd[e][c] = r;
        }

    float4 a_reg[2];
    float4 b_reg[2];

    auto loadA = [&](int k0) {
#pragma unroll
        for (int e = 0; e < 2; e++)
            a_reg[e] = *reinterpret_cast<const float4*>(
                &g_h[(size_t)(row0 + a_m4[e]) * K + k0 + a_kc[e]]);
    };
    auto loadB = [&](int k0) {
#pragma unroll
        for (int e = 0; e < 2; e++) {
            int kg = k0 + b_k[e];
            int kgm = kg;
            while (kgm >= Dm1) kgm -= Dm1;
            float4 v = *reinterpret_cast<const float4*>(
                &W2[(size_t)kg * N + col0 + b_n[e]]);
            if (!(jd[e][0] > kgm)) v.x = 0.f;
            if (!(jd[e][1] > kgm)) v.y = 0.f;
            if (!(jd[e][2] > kgm)) v.z = 0.f;
            if (!(jd[e][3] > kgm)) v.w = 0.f;
            b_reg[e] = v;
        }
    };
    auto storeAB = [&]() {
#pragma unroll
        for (int e = 0; e < 2; e++) {
            As[a_kc[e] + 0][a_m4[e]] = a_reg[e].x;
            As[a_kc[e] + 1][a_m4[e]] = a_reg[e].y;
            As[a_kc[e] + 2][a_m4[e]] = a_reg[e].z;
            As[a_kc[e] + 3][a_m4[e]] = a_reg[e].w;
        }
#pragma unroll
        for (int e = 0; e < 2; e++)
            *reinterpret_cast<float4*>(&Bs[b_k[e]][b_n[e]]) = b_reg[e];
    };

    loadA(0);
    loadB(0);
    storeAB();
    __syncthreads();

    const int nk = K / TBK;
    for (int t = 0; t < nk; t++) {
        const bool has_next = (t + 1 < nk);
        if (has_next) { loadA((t + 1) * TBK); loadB((t + 1) * TBK); }
#pragma unroll
        for (int k = 0; k < TBK; k++) {
            const float4 a0  = *reinterpret_cast<const float4*>(&As[k][ty * TTM]);
            const float4 a1  = *reinterpret_cast<const float4*>(&As[k][ty * TTM + 4]);
            const float4 bb0 = *reinterpret_cast<const float4*>(&Bs[k][tx * TTN]);
            const float4 bb1 = *reinterpret_cast<const float4*>(&Bs[k][tx * TTN + 4]);
            unsigned long long av[8];
            av[0] = pack_dup(a0.x); av[1] = pack_dup(a0.y);
            av[2] = pack_dup(a0.z); av[3] = pack_dup(a0.w);
            av[4] = pack_dup(a1.x); av[5] = pack_dup(a1.y);
            av[6] = pack_dup(a1.z); av[7] = pack_dup(a1.w);
            unsigned long long bv[4];
            bv[0] = pack2(bb0.x, bb0.y); bv[1] = pack2(bb0.z, bb0.w);
            bv[2] = pack2(bb1.x, bb1.y); bv[3] = pack2(bb1.z, bb1.w);
#pragma unroll
            for (int m = 0; m < TTM; m++)
#pragma unroll
                for (int n = 0; n < TTN / 2; n++)
                    ffma2(acc[m][n], av[m], bv[n]);
        }
        __syncthreads();
        if (has_next) { storeAB(); __syncthreads(); }
    }

    // epilogue: + b2, store to g_res (no relu)
    float bias[TTN];
#pragma unroll
    for (int n = 0; n < TTN; n++) bias[n] = b2[col0 + tx * TTN + n];
#pragma unroll
    for (int m = 0; m < TTM; m++) {
        int r = row0 + ty * TTM + m;
        float v[TTN];
#pragma unroll
        for (int n = 0; n < TTN / 2; n++) unpack2(acc[m][n], v[2 * n], v[2 * n + 1]);
        float4 o0, o1;
        o0.x = v[0] + bias[0];
        o0.y = v[1] + bias[1];
        o0.z = v[2] + bias[2];
        o0.w = v[3] + bias[3];
        o1.x = v[4] + bias[4];
        o1.y = v[5] + bias[5];
        o1.z = v[6] + bias[6];
        o1.w = v[7] + bias[7];
        float* orow = &g_res[(size_t)r * N + col0 + tx * TTN];
        *reinterpret_cast<float4*>(orow)     = o0;
        *reinterpret_cast<float4*>(orow + 4) = o1;
    }
}

// =====================================================================
// finish: x_out[i,j] = zp[i,inv[j]] * exp(log_s[i,inv[j]]) + mu[i,inv[j]]
//         log_det[i] = sum_d log_s[i,d]
// zp[i, inv[j]] = z[i, perm[inv[j]]]
// =====================================================================
__global__ void finish_kernel(const float* __restrict__ z,
                              const int* __restrict__ perm,
                              float* __restrict__ out,
                              int Bn, int D)
{
    const int i = blockIdx.x;
    const int t = threadIdx.x;
    __shared__ float red[256];

    const float* resrow = &g_res[(size_t)i * 2 * D];
    const float* zrow   = &z[(size_t)i * D];

    float s = 0.f;
    for (int d = t; d < D; d += blockDim.x) s += resrow[D + d];

    for (int j = t; j < D; j += blockDim.x) {
        int dj   = g_inv[j];
        float ls = resrow[D + dj];
        float mu = resrow[dj];
        float zp = zrow[perm[dj]];
        out[(size_t)i * D + j] = fmaf(zp, expf(ls), mu);
    }

    red[t] = s;
    __syncthreads();
    for (int off = 128; off > 0; off >>= 1) {
        if (t < off) red[t] += red[t + off];
        __syncthreads();
    }
    if (t == 0) out[(size_t)Bn * D + i] = red[0];
}

extern "C" void kernel_launch(void* const* d_in, const int* in_sizes, int n_in,
                              void* d_out, int out_size) {
    const float* z    = (const float*)d_in[0];
    const float* W1   = (const float*)d_in[1];
    const float* b1   = (const float*)d_in[2];
    const float* W2   = (const float*)d_in[3];
    const float* b2   = (const float*)d_in[4];
    const int*   perm = (const int*)d_in[5];

    const int D   = in_sizes[5];     // 1024
    const int H   = in_sizes[2];     // 4096
    const int N2  = in_sizes[4];     // 2048
    const int B   = in_sizes[0] / D; // 4096
    const int Dm1 = D - 1;

    build_inv<<<(D + 255) / 256, 256>>>(perm, D);
    gemm1_kernel<<<dim3(H / TBN, B / TBM), NTHR>>>(z, W1, b1, perm, B, H, D, Dm1);
    gemm2_kernel<<<dim3(N2 / TBN, B / TBM), NTHR>>>(W2, b2, B, N2, H, D, Dm1);
    finish_kernel<<<B, 256>>>(z, perm, (float*)d_out, B, D);
}

// round 4
// speedup vs baseline: 2.6227x; 2.6227x over previous
#include <cuda_runtime.h>
#include <cuda_bf16.h>
#include <cstdint>

// ============================================================
// MADE/IAF flow step on tensor cores via mma.sync (bf16, HMMA),
// fp32 accuracy via 3-term bf16 split: x*y ~= hi*hi + lo*hi + hi*lo
// GEMM1: h = relu(zp @ (W1*M1) + b1)   [4096,1024]x[1024,4096]
// GEMM2: res = h @ (W2*M2) + b2        [4096,4096]x[4096,2048]
// finish: x = zp*exp(log_s)+mu (inv-permuted), log_det = row-sum
// ============================================================

// ---------------- device scratch (no allocs allowed) ----------------
__device__ float         g_res[4096ull * 2048ull];   // gemm2 out (fp32)
__device__ int           g_inv[4096];
__device__ __nv_bfloat16 g_zhi[4096ull * 1024ull], g_zlo[4096ull * 1024ull];   // [B,D]
__device__ __nv_bfloat16 g_w1hi[4096ull * 1024ull], g_w1lo[4096ull * 1024ull]; // [N=4096,K=1024]
__device__ __nv_bfloat16 g_hhi[4096ull * 4096ull], g_hlo[4096ull * 4096ull];   // [B,H]
__device__ __nv_bfloat16 g_w2hi[2048ull * 4096ull], g_w2lo[2048ull * 4096ull]; // [N=2048,K=4096]

// ---------------- PTX helpers (all baseline sm_80+ PTX) ----------------
__device__ __forceinline__ uint32_t smem_u32(const void* p) {
    uint32_t a;
    asm("{ .reg .u64 t; cvta.to.shared.u64 t, %1; cvt.u32.u64 %0, t; }" : "=r"(a) : "l"(p));
    return a;
}
__device__ __forceinline__ void cp16(uint32_t s, const void* g) {
    asm volatile("cp.async.cg.shared.global [%0], [%1], 16;" :: "r"(s), "l"(g));
}
__device__ __forceinline__ void cp_commit() {
    asm volatile("cp.async.commit_group;" ::: "memory");
}
__device__ __forceinline__ void cp_wait1() {
    asm volatile("cp.async.wait_group 1;" ::: "memory");
}
__device__ __forceinline__ void ldm_x4(uint32_t addr, uint32_t* r) {
    asm volatile("ldmatrix.sync.aligned.m8n8.x4.shared.b16 {%0,%1,%2,%3}, [%4];"
                 : "=r"(r[0]), "=r"(r[1]), "=r"(r[2]), "=r"(r[3]) : "r"(addr));
}
__device__ __forceinline__ void mma16816(float* c, const uint32_t* a, const uint32_t* b) {
    asm volatile(
        "mma.sync.aligned.m16n8k16.row.col.f32.bf16.bf16.f32 "
        "{%0,%1,%2,%3}, {%4,%5,%6,%7}, {%8,%9}, {%0,%1,%2,%3};"
        : "+f"(c[0]), "+f"(c[1]), "+f"(c[2]), "+f"(c[3])
        : "r"(a[0]), "r"(a[1]), "r"(a[2]), "r"(a[3]), "r"(b[0]), "r"(b[1]));
}

// ---------------- prep kernels ----------------
__global__ void build_inv(const int* __restrict__ perm, int D) {
    int d = blockIdx.x * blockDim.x + threadIdx.x;
    if (d < D) g_inv[perm[d]] = d;
}

__global__ void split_z_kernel(const float* __restrict__ z, const int* __restrict__ perm,
                               int D, long total) {
    long idx = (long)blockIdx.x * blockDim.x + threadIdx.x;
    if (idx >= total) return;
    int i = (int)(idx >> 10);      // D = 1024
    int k = (int)(idx & 1023);
    float v = z[(size_t)i * D + perm[k]];
    __nv_bfloat16 hi = __float2bfloat16(v);
    __nv_bfloat16 lo = __float2bfloat16(v - __bfloat162float(hi));
    g_zhi[idx] = hi;
    g_zlo[idx] = lo;
}

// mask+transpose+split: in W [K,N] fp32 -> out [N,K] bf16 hi/lo
// mode 1: mask = (n % 1023) >= k          (W1/M1)
// mode 2: mask = (n % 1024) > (k % 1023)  (W2/M2)
__global__ void prep_w_kernel(const float* __restrict__ W,
                              __nv_bfloat16* __restrict__ oHi, __nv_bfloat16* __restrict__ oLo,
                              int K, int N, int mode) {
    __shared__ float tile[32][33];
    const int k0 = blockIdx.y * 32;
    const int n0 = blockIdx.x * 32;
    const int tx = threadIdx.x;   // 32
    const int ty = threadIdx.y;   // 8
#pragma unroll
    for (int j = 0; j < 32; j += 8)
        tile[ty + j][tx] = W[(size_t)(k0 + ty + j) * N + n0 + tx];
    __syncthreads();
#pragma unroll
    for (int j = 0; j < 32; j += 8) {
        int n = n0 + ty + j;
        int k = k0 + tx;
        float v = tile[tx][ty + j];
        bool m;
        if (mode == 1) m = (n % 1023) >= k;
        else           m = (n % 1024) > (k % 1023);
        v = m ? v : 0.0f;
        __nv_bfloat16 hi = __float2bfloat16(v);
        __nv_bfloat16 lo = __float2bfloat16(v - __bfloat162float(hi));
        oHi[(size_t)n * K + k] = hi;
        oLo[(size_t)n * K + k] = lo;
    }
}

// ---------------- mma.sync GEMM (3-term bf16 split) ----------------
// C[m,n] = sum_k A[m,k]*B[n,k]; A [M,K] row-major hi/lo, B [N,K] row-major hi/lo.
// CTA tile 128x128, K-chunk 32, 8 warps (2x4), warp tile 64x32, 3-stage cp.async.
// Smem row layout: 128 rows x 128B; bytes [0,64) = hi k0..31, [64,128) = lo k0..31,
// XOR-swizzled so ldmatrix is conflict-free: byte = row*128 + (inner ^ ((row&7)<<4)).
#define SA_BYTES   16384
#define STG_BYTES  32768
#define SM_TOTAL   (3 * STG_BYTES)

template <int MODE>
__global__ __launch_bounds__(256, 1) void gemm_mma(
    const __nv_bfloat16* __restrict__ Ahi, const __nv_bfloat16* __restrict__ Alo,
    const __nv_bfloat16* __restrict__ Bhi, const __nv_bfloat16* __restrict__ Blo,
    const float* __restrict__ bias, int K, int Nout,
    float* __restrict__ outF,
    __nv_bfloat16* __restrict__ outHi, __nv_bfloat16* __restrict__ outLo)
{
    extern __shared__ char smem[];
    const uint32_t sb = smem_u32(smem);
    const int tid  = threadIdx.x;
    const int lane = tid & 31;
    const int w    = tid >> 5;
    const int wm   = w & 1;        // 2 warps in M
    const int wn   = w >> 1;       // 4 warps in N
    const int row0 = blockIdx.y * 128;
    const int col0 = blockIdx.x * 128;
    const int nk   = K >> 5;

    float acc[4][4][4];
#pragma unroll
    for (int mt = 0; mt < 4; mt++)
#pragma unroll
        for (int nt = 0; nt < 4; nt++)
#pragma unroll
            for (int e = 0; e < 4; e++) acc[mt][nt][e] = 0.f;

    auto load_stage = [&](int t) {
        const int k0 = t << 5;
        const uint32_t s0 = sb + (t % 3) * STG_BYTES;
#pragma unroll
        for (int i = 0; i < 4; i++) {
            int idx = tid + i * 256;
            int row = idx >> 3, cc = idx & 7;
            const __nv_bfloat16* src =
                ((cc < 4) ? Ahi : Alo) + (size_t)(row0 + row) * K + k0 + (cc & 3) * 8;
            cp16(s0 + row * 128 + ((cc * 16) ^ ((row & 7) << 4)), src);
        }
#pragma unroll
        for (int i = 0; i < 4; i++) {
            int idx = tid + i * 256;
            int row = idx >> 3, cc = idx & 7;
            const __nv_bfloat16* src =
                ((cc < 4) ? Bhi : Blo) + (size_t)(col0 + row) * K + k0 + (cc & 3) * 8;
            cp16(s0 + SA_BYTES + row * 128 + ((cc * 16) ^ ((row & 7) << 4)), src);
        }
    };

    load_stage(0); cp_commit();
    load_stage(1); cp_commit();

    // fragment address components (per-thread constants)
    int rA[4], xA[4];
#pragma unroll
    for (int mt = 0; mt < 4; mt++) {
        int r = wm * 64 + mt * 16 + (lane & 15);
        rA[mt] = r * 128;
        xA[mt] = (r & 7) << 4;
    }
    const int kA2 = (lane >> 4) << 4;          // A k-byte offset part (0 or 16)
    int rB[2], xB[2];
#pragma unroll
    for (int p = 0; p < 2; p++) {
        int r = wn * 32 + p * 16 + (lane & 7) + ((lane & 16) >> 1);
        rB[p] = r * 128;
        xB[p] = (r & 7) << 4;
    }
    const int kB2 = (lane & 8) << 1;           // B k-byte offset part (0 or 16)

    for (int t = 0; t < nk; t++) {
        cp_wait1();
        __syncthreads();
        if (t + 2 < nk) load_stage(t + 2);
        cp_commit();

        const uint32_t sA = sb + (t % 3) * STG_BYTES;
        const uint32_t sB = sA + SA_BYTES;
#pragma unroll
        for (int ks = 0; ks < 2; ks++) {
            uint32_t Ah[4][4], Al[4][4], Bh[4][2], Bl[4][2];
            const int kbA = ks * 32 + kA2;
            const int kbB = ks * 32 + kB2;
#pragma unroll
            for (int mt = 0; mt < 4; mt++)
                ldm_x4(sA + rA[mt] + (kbA ^ xA[mt]), Ah[mt]);
#pragma unroll
            for (int mt = 0; mt < 4; mt++)
                ldm_x4(sA + rA[mt] + ((64 + kbA) ^ xA[mt]), Al[mt]);
#pragma unroll
            for (int p = 0; p < 2; p++) {
                uint32_t r4[4];
                ldm_x4(sB + rB[p] + (kbB ^ xB[p]), r4);
                Bh[2 * p][0] = r4[0]; Bh[2 * p][1] = r4[1];
                Bh[2 * p + 1][0] = r4[2]; Bh[2 * p + 1][1] = r4[3];
            }
#pragma unroll
            for (int p = 0; p < 2; p++) {
                uint32_t r4[4];
                ldm_x4(sB + rB[p] + ((64 + kbB) ^ xB[p]), r4);
                Bl[2 * p][0] = r4[0]; Bl[2 * p][1] = r4[1];
                Bl[2 * p + 1][0] = r4[2]; Bl[2 * p + 1][1] = r4[3];
            }
            // hi*hi
#pragma unroll
            for (int mt = 0; mt < 4; mt++)
#pragma unroll
                for (int nt = 0; nt < 4; nt++)
                    mma16816(acc[mt][nt], Ah[mt], Bh[nt]);
            // lo*hi
#pragma unroll
            for (int mt = 0; mt < 4; mt++)
#pragma unroll
                for (int nt = 0; nt < 4; nt++)
                    mma16816(acc[mt][nt], Al[mt], Bh[nt]);
            // hi*lo
#pragma unroll
            for (int mt = 0; mt < 4; mt++)
#pragma unroll
                for (int nt = 0; nt < 4; nt++)
                    mma16816(acc[mt][nt], Ah[mt], Bl[nt]);
        }
    }

    // epilogue
    const int mrow = lane >> 2;
    const int mcol = (lane & 3) * 2;
#pragma unroll
    for (int mt = 0; mt < 4; mt++) {
        const int rbase = row0 + wm * 64 + mt * 16 + mrow;
#pragma unroll
        for (int nt = 0; nt < 4; nt++) {
            const int c = col0 + wn * 32 + nt * 8 + mcol;
            const float b0 = bias[c], b1 = bias[c + 1];
#pragma unroll
            for (int h = 0; h < 2; h++) {
                const int r = rbase + h * 8;
                float v0 = acc[mt][nt][2 * h + 0] + b0;
                float v1 = acc[mt][nt][2 * h + 1] + b1;
                const size_t o = (size_t)r * Nout + c;
                if (MODE == 1) {
                    v0 = fmaxf(v0, 0.f);
                    v1 = fmaxf(v1, 0.f);
                    __nv_bfloat16 h0 = __float2bfloat16(v0);
                    __nv_bfloat16 h1 = __float2bfloat16(v1);
                    __nv_bfloat16 l0 = __float2bfloat16(v0 - __bfloat162float(h0));
                    __nv_bfloat16 l1 = __float2bfloat16(v1 - __bfloat162float(h1));
                    __nv_bfloat162 ph; ph.x = h0; ph.y = h1;
                    __nv_bfloat162 pl; pl.x = l0; pl.y = l1;
                    *(__nv_bfloat162*)(outHi + o) = ph;
                    *(__nv_bfloat162*)(outLo + o) = pl;
                } else {
                    *(float2*)(outF + o) = make_float2(v0, v1);
                }
            }
        }
    }
}

// ---------------- finish ----------------
__global__ void finish_kernel(const float* __restrict__ z,
                              const int* __restrict__ perm,
                              float* __restrict__ out,
                              int Bn, int D)
{
    const int i = blockIdx.x;
    const int t = threadIdx.x;
    __shared__ float red[256];

    const float* resrow = &g_res[(size_t)i * 2 * D];
    const float* zrow   = &z[(size_t)i * D];

    float s = 0.f;
    for (int d = t; d < D; d += blockDim.x) s += resrow[D + d];

    for (int j = t; j < D; j += blockDim.x) {
        int dj   = g_inv[j];
        float ls = resrow[D + dj];
        float mu = resrow[dj];
        float zp = zrow[perm[dj]];
        out[(size_t)i * D + j] = fmaf(zp, expf(ls), mu);
    }

    red[t] = s;
    __syncthreads();
    for (int off = 128; off > 0; off >>= 1) {
        if (t < off) red[t] += red[t + off];
        __syncthreads();
    }
    if (t == 0) out[(size_t)Bn * D + i] = red[0];
}

// ---------------- launch ----------------
extern "C" void kernel_launch(void* const* d_in, const int* in_sizes, int n_in,
                              void* d_out, int out_size) {
    const float* z    = (const float*)d_in[0];
    const float* W1   = (const float*)d_in[1];
    const float* b1   = (const float*)d_in[2];
    const float* W2   = (const float*)d_in[3];
    const float* b2   = (const float*)d_in[4];
    const int*   perm = (const int*)d_in[5];

    const int D  = in_sizes[5];      // 1024
    const int H  = in_sizes[2];      // 4096
    const int N2 = in_sizes[4];      // 2048
    const int B  = in_sizes[0] / D;  // 4096

    cudaFuncSetAttribute(gemm_mma<1>, cudaFuncAttributeMaxDynamicSharedMemorySize, SM_TOTAL);
    cudaFuncSetAttribute(gemm_mma<2>, cudaFuncAttributeMaxDynamicSharedMemorySize, SM_TOTAL);

    __nv_bfloat16 *zhi, *zlo, *w1hi, *w1lo, *hhi, *hlo, *w2hi, *w2lo;
    float* res;
    cudaGetSymbolAddress((void**)&zhi,  g_zhi);
    cudaGetSymbolAddress((void**)&zlo,  g_zlo);
    cudaGetSymbolAddress((void**)&w1hi, g_w1hi);
    cudaGetSymbolAddress((void**)&w1lo, g_w1lo);
    cudaGetSymbolAddress((void**)&hhi,  g_hhi);
    cudaGetSymbolAddress((void**)&hlo,  g_hlo);
    cudaGetSymbolAddress((void**)&w2hi, g_w2hi);
    cudaGetSymbolAddress((void**)&w2lo, g_w2lo);
    cudaGetSymbolAddress((void**)&res,  g_res);

    build_inv<<<(D + 255) / 256, 256>>>(perm, D);
    split_z_kernel<<<(long)B * D / 256, 256>>>(z, perm, D, (long)B * D);
    prep_w_kernel<<<dim3(H / 32, D / 32),  dim3(32, 8)>>>(W1, w1hi, w1lo, D, H, 1);
    prep_w_kernel<<<dim3(N2 / 32, H / 32), dim3(32, 8)>>>(W2, w2hi, w2lo, H, N2, 2);

    // GEMM1: [B,D] x [D,H]^T-packed -> h (bf16 split)
    gemm_mma<1><<<dim3(H / 128, B / 128), 256, SM_TOTAL>>>(
        zhi, zlo, w1hi, w1lo, b1, D, H, nullptr, hhi, hlo);
    // GEMM2: [B,H] x [H,2D]^T-packed -> res (fp32)
    gemm_mma<2><<<dim3(N2 / 128, B / 128), 256, SM_TOTAL>>>(
        hhi, hlo, w2hi, w2lo, b2, H, N2, res, nullptr, nullptr);

    finish_kernel<<<B, 256>>>(z, perm, (float*)d_out, B, D);
}